// round 12
// baseline (speedup 1.0000x reference)
#include <cuda_runtime.h>
#include <cuda_fp16.h>
#include <cstdint>
#include <cstddef>

#define BB 128
#define SS 1024
#define II 512
#define HH 1024
#define GG 4096
#define NCTA2 128

__device__ __half g_x_h[(size_t)BB * SS * II];
__device__ __half g_Wx_h[(size_t)GG * II];
__device__ __half g_Wh_h[(size_t)GG * HH];
__device__ float  g_bsum[GG];
__device__ __half g_xg[(size_t)SS * BB * GG];   // [S][B][4H]
__device__ __half g_h16[2][BB * HH];
__device__ float  g_h32[BB * HH];
__device__ unsigned g_bar_count;
__device__ unsigned g_bar_gen;

__device__ __forceinline__ uint32_t smem_u32(const void* p) {
    return (uint32_t)__cvta_generic_to_shared(p);
}
__device__ __forceinline__ void cp_async16(void* dst, const void* src) {
    // .cg: bypass L1 (h is written by other SMs; L1 is per-SM incoherent)
    asm volatile("cp.async.cg.shared.global [%0], [%1], 16;\n" ::"r"(smem_u32(dst)), "l"(src));
}
__device__ __forceinline__ void cp_commit() { asm volatile("cp.async.commit_group;\n"); }
template <int N>
__device__ __forceinline__ void cp_wait() { asm volatile("cp.async.wait_group %0;\n" ::"n"(N)); }

__device__ __forceinline__ void ldsm_x4(uint32_t (&r)[4], const void* p) {
    asm volatile("ldmatrix.sync.aligned.m8n8.x4.shared.b16 {%0,%1,%2,%3}, [%4];\n"
                 : "=r"(r[0]), "=r"(r[1]), "=r"(r[2]), "=r"(r[3]) : "r"(smem_u32(p)));
}
__device__ __forceinline__ void mma16816(float (&d)[4], const uint32_t (&a)[4],
                                         uint32_t b0, uint32_t b1) {
    asm volatile("mma.sync.aligned.m16n8k16.row.col.f32.f16.f16.f32 "
                 "{%0,%1,%2,%3}, {%4,%5,%6,%7}, {%8,%9}, {%0,%1,%2,%3};\n"
                 : "+f"(d[0]), "+f"(d[1]), "+f"(d[2]), "+f"(d[3])
                 : "r"(a[0]), "r"(a[1]), "r"(a[2]), "r"(a[3]), "r"(b0), "r"(b1));
}
__device__ __forceinline__ float tanh_a(float x) {
    float y; asm("tanh.approx.f32 %0, %1;" : "=f"(y) : "f"(x)); return y;
}
__device__ __forceinline__ float sigm(float x) { return fmaf(tanh_a(0.5f * x), 0.5f, 0.5f); }

// ---------------- init ----------------
__global__ void lstm_prep_w(const float* __restrict__ Wx, const float* __restrict__ Wh,
                            const float* __restrict__ bW, const float* __restrict__ bU) {
    int stride = gridDim.x * blockDim.x;
    int i0 = blockIdx.x * blockDim.x + threadIdx.x;
    for (int i = i0; i < GG * HH; i += stride) g_Wh_h[i] = __float2half(Wh[i]);
    for (int i = i0; i < GG * II; i += stride) g_Wx_h[i] = __float2half(Wx[i]);
    if (i0 < GG) g_bsum[i0] = bW[i0] + bU[i0];
    if (i0 < BB * HH) { g_h16[0][i0] = __float2half(0.f); g_h16[1][i0] = __float2half(0.f); }
    if (i0 == 0) { g_bar_count = 0u; g_bar_gen = 0u; }
}
__global__ void lstm_prep_x(const float* __restrict__ x) {
    int stride = gridDim.x * blockDim.x;
    for (int i = blockIdx.x * blockDim.x + threadIdx.x; i < BB * SS * II; i += stride)
        g_x_h[i] = __float2half(x[i]);
}

// ---------------- phase 1: xg = x @ Wx^T + bsum  (unchanged, known-good) ----------------
#define P1_SMEM (2 * 2 * 128 * 72 * 2)
__global__ void __launch_bounds__(256) lstm_xproj() {
    extern __shared__ __half sm1[];
    __half* As = sm1;
    __half* Bs = sm1 + 2 * 128 * 72;
    const int tid = threadIdx.x, lane = tid & 31, wid = tid >> 5;
    const int wm = wid >> 1, wn = wid & 1;
    const int n0 = blockIdx.x * 128, sblk = blockIdx.y;
    float acc[2][8][4];
#pragma unroll
    for (int mi = 0; mi < 2; ++mi)
#pragma unroll
        for (int f = 0; f < 8; ++f)
#pragma unroll
            for (int u = 0; u < 4; ++u) acc[mi][f][u] = 0.f;
#define P1_LOAD(buf, kc)                                                           \
    {                                                                              \
        int k0_ = (kc) * 64;                                                       \
        _Pragma("unroll") for (int it = 0; it < 4; ++it) {                         \
            int task = tid + it * 256, row = task >> 3, seg = task & 7;            \
            cp_async16(&As[(buf) * 9216 + row * 72 + seg * 8],                     \
                       g_x_h + ((size_t)row * SS + sblk) * II + k0_ + seg * 8);    \
            cp_async16(&Bs[(buf) * 9216 + row * 72 + seg * 8],                     \
                       g_Wx_h + (size_t)(n0 + row) * II + k0_ + seg * 8);          \
        }                                                                          \
    }
    P1_LOAD(0, 0);
    cp_commit();
#pragma unroll 1
    for (int kc = 0; kc < 8; ++kc) {
        int buf = kc & 1;
        if (kc < 7) { P1_LOAD(buf ^ 1, kc + 1); cp_commit(); cp_wait<1>(); }
        else        { cp_wait<0>(); }
        __syncthreads();
#pragma unroll
        for (int kk = 0; kk < 4; ++kk) {
            uint32_t a[2][4];
#pragma unroll
            for (int mi = 0; mi < 2; ++mi)
                ldsm_x4(a[mi], &As[buf * 9216 + (wm * 32 + mi * 16 + (lane & 15)) * 72 +
                                   kk * 16 + (lane >> 4) * 8]);
#pragma unroll
            for (int nj = 0; nj < 4; ++nj) {
                uint32_t b4[4];
                ldsm_x4(b4, &Bs[buf * 9216 + (wn * 64 + nj * 16 + (lane & 15)) * 72 +
                                kk * 16 + (lane >> 4) * 8]);
#pragma unroll
                for (int mi = 0; mi < 2; ++mi) {
                    mma16816(acc[mi][nj * 2 + 0], a[mi], b4[0], b4[2]);
                    mma16816(acc[mi][nj * 2 + 1], a[mi], b4[1], b4[3]);
                }
            }
        }
        __syncthreads();
    }
    const int r = lane >> 2, c2 = (lane & 3) * 2;
    const size_t mbase = (size_t)sblk * 128;
#pragma unroll
    for (int mi = 0; mi < 2; ++mi) {
        int mrow = wm * 32 + mi * 16 + r;
#pragma unroll
        for (int f = 0; f < 8; ++f) {
            int col = n0 + wn * 64 + f * 8 + c2;
            float b0 = g_bsum[col], b1 = g_bsum[col + 1];
            *(__half2*)(g_xg + (mbase + mrow) * (size_t)GG + col) =
                __floats2half2_rn(acc[mi][f][0] + b0, acc[mi][f][1] + b1);
            *(__half2*)(g_xg + (mbase + mrow + 8) * (size_t)GG + col) =
                __floats2half2_rn(acc[mi][f][2] + b0, acc[mi][f][3] + b1);
        }
    }
}

// ---------------- phase 2: persistent recurrence, 512 threads, K-split x2 ----------------
// 128 CTAs: ms = blk>>6 (64 B-rows), ns = blk&63 (16 h-cols -> 64 gate rows).
// 16 warps: kh = wid&1 (K half), wn = (wid>>1)&3 (16 gate cols), wm = wid>>3 (32 B-rows).
// SMEM: Whs 64x1032 halves (132096B) | 4 h-chunk buffers x 17408B.
// Gs0 aliases buf0, Gs1 aliases buf1 (dead by the time partials are written).
#define WHS_STRIDE 1032
#define HCH_STRIDE 136
#define GS_STRIDE  68
#define HBUF (64 * HCH_STRIDE)
#define P2_SMEM (132096 + 4 * 17408) /* 201728 B -> 1 CTA/SM */

__global__ void __launch_bounds__(512, 1) lstm_rec() {
    extern __shared__ unsigned char smraw[];
    __half* Whs = (__half*)smraw;
    __half* Hs  = (__half*)(smraw + 132096);
    float*  Gs0 = (float*)(smraw + 132096);            // aliases h buf0
    float*  Gs1 = (float*)(smraw + 132096 + 17408);    // aliases h buf1
    const int tid = threadIdx.x, lane = tid & 31, wid = tid >> 5;
    const int kh = wid & 1, wn = (wid >> 1) & 3, wm = wid >> 3;
    const int ms = blockIdx.x >> 6, ns = blockIdx.x & 63;

    // resident Wh slice: row j -> gate (j>>4), h-col ns*16+(j&15)
#pragma unroll 4
    for (int it = 0; it < 16; ++it) {
        int task = tid + it * 512;
        int j = task >> 7, seg = task & 127;
        int grow = (j >> 4) * HH + ns * 16 + (j & 15);
        cp_async16(&Whs[j * WHS_STRIDE + seg * 8], g_Wh_h + (size_t)grow * HH + seg * 8);
    }
    cp_commit();
    cp_wait<0>();
    __syncthreads();

    const int hc = tid & 15, brow0 = tid >> 4;   // brow0: 0..31; cells (brow0, hc),(brow0+32, hc)
    float cst[2] = {0.f, 0.f};

#define H_LOAD(buf, kc)                                                            \
    {                                                                              \
        _Pragma("unroll") for (int it = 0; it < 2; ++it) {                         \
            int task = tid + it * 512, row = task >> 4, seg = task & 15;           \
            cp_async16(&Hs[(buf) * HBUF + row * HCH_STRIDE + seg * 8],             \
                       hsrc + (size_t)row * HH + (kc) * 128 + seg * 8);            \
        }                                                                          \
        cp_commit();                                                               \
    }
#define XG_PREFETCH(tt)                                                            \
    {                                                                              \
        const __half* xp = g_xg + ((size_t)(tt) * BB + ms * 64) * GG + ns * 16 + hc; \
        _Pragma("unroll") for (int k = 0; k < 2; ++k) {                            \
            size_t bo = (size_t)(brow0 + k * 32) * GG;                             \
            _Pragma("unroll") for (int g = 0; g < 4; ++g)                          \
                xh[k][g] = __ldg(xp + bo + g * HH);                                \
        }                                                                          \
    }

    __half xh[2][4];
    XG_PREFETCH(0);

    for (int t = 0; t < SS; ++t) {
        const int par = t & 1;
        const __half* hsrc = g_h16[par] + (size_t)(ms * 64) * HH;

        // wait for all CTAs to finish step t-1 (gen == t); xg for step t already in regs
        if (t > 0) {
            if (tid == 0) {
                unsigned cur;
                do {
                    asm volatile("ld.acquire.gpu.b32 %0, [%1];"
                                 : "=r"(cur) : "l"(&g_bar_gen) : "memory");
                } while (cur < (unsigned)t);
            }
            __syncthreads();
        }

        float acc[2][2][4];
#pragma unroll
        for (int mi = 0; mi < 2; ++mi)
#pragma unroll
            for (int nh = 0; nh < 2; ++nh)
#pragma unroll
                for (int u = 0; u < 4; ++u) acc[mi][nh][u] = 0.f;

        H_LOAD(0, 0);
        H_LOAD(1, 1);
        H_LOAD(2, 2);
#pragma unroll 1
        for (int kc = 0; kc < 8; ++kc) {
            if (kc < 6)       cp_wait<2>();
            else if (kc == 6) cp_wait<1>();
            else              cp_wait<0>();
            __syncthreads();
            if (kc < 5) H_LOAD((kc + 3) & 3, kc + 3);
            const int buf = kc & 3;
#pragma unroll
            for (int kk2 = 0; kk2 < 4; ++kk2) {
                const int kk = kh * 4 + kk2;
                uint32_t a[2][4];
#pragma unroll
                for (int mi = 0; mi < 2; ++mi)
                    ldsm_x4(a[mi], &Hs[buf * HBUF +
                                       (wm * 32 + mi * 16 + (lane & 15)) * HCH_STRIDE +
                                       kk * 16 + (lane >> 4) * 8]);
                uint32_t b4[4];
                ldsm_x4(b4, &Whs[(wn * 16 + (lane & 15)) * WHS_STRIDE +
                                 kc * 128 + kk * 16 + (lane >> 4) * 8]);
#pragma unroll
                for (int mi = 0; mi < 2; ++mi) {
                    mma16816(acc[mi][0], a[mi], b4[0], b4[2]);
                    mma16816(acc[mi][1], a[mi], b4[1], b4[3]);
                }
            }
        }

        // write K-half partial gate tiles (transposed) to Gs0/Gs1
        {
            float* G = kh ? Gs1 : Gs0;
            int r = lane >> 2, c2 = (lane & 3) * 2;
#pragma unroll
            for (int mi = 0; mi < 2; ++mi)
#pragma unroll
                for (int nh = 0; nh < 2; ++nh) {
                    int col = wn * 16 + nh * 8 + c2;
                    int row = wm * 32 + mi * 16 + r;
                    G[row * GS_STRIDE + col]           = acc[mi][nh][0];
                    G[row * GS_STRIDE + col + 1]       = acc[mi][nh][1];
                    G[(row + 8) * GS_STRIDE + col]     = acc[mi][nh][2];
                    G[(row + 8) * GS_STRIDE + col + 1] = acc[mi][nh][3];
                }
        }
        __syncthreads();

        // elementwise: 2 cells/thread; c in registers; h fp16 to the other buffer
        __half* hdst = g_h16[par ^ 1] + (size_t)(ms * 64) * HH + ns * 16 + hc;
#pragma unroll
        for (int k = 0; k < 2; ++k) {
            int b = brow0 + k * 32;
            int base = b * GS_STRIDE + hc;
            float fv = Gs0[base]      + Gs1[base]      + __half2float(xh[k][0]);
            float iv = Gs0[base + 16] + Gs1[base + 16] + __half2float(xh[k][1]);
            float gv = Gs0[base + 32] + Gs1[base + 32] + __half2float(xh[k][2]);
            float ov = Gs0[base + 48] + Gs1[base + 48] + __half2float(xh[k][3]);
            cst[k] = sigm(fv) * cst[k] + sigm(iv) * tanh_a(gv);
            float hv = sigm(ov) * tanh_a(cst[k]);
            hdst[(size_t)b * HH] = __float2half(hv);
            if (t == SS - 1) g_h32[(size_t)(ms * 64 + b) * HH + ns * 16 + hc] = hv;
        }

        // arrive (release h stores), then prefetch next xg while others finish
        __threadfence();
        __syncthreads();
        if (tid == 0) {
            unsigned old = atomicAdd(&g_bar_count, 1u);
            if (old == (unsigned)(NCTA2 - 1)) {
                *(volatile unsigned*)&g_bar_count = 0u;
                __threadfence();
                atomicAdd(&g_bar_gen, 1u);
            }
        }
        if (t + 1 < SS) XG_PREFETCH(t + 1);
    }
}

// ---------------- head ----------------
__global__ void lstm_head(const float* __restrict__ fc_w, const float* __restrict__ fc_b,
                          float* __restrict__ out) {
    __shared__ float hrow[HH];
    int b = blockIdx.x;
    for (int i = threadIdx.x; i < HH; i += 128) hrow[i] = g_h32[(size_t)b * HH + i];
    __syncthreads();
    int o = threadIdx.x;
    const float4* wp = (const float4*)(fc_w + (size_t)o * HH);
    float s = 0.f;
#pragma unroll 4
    for (int i = 0; i < HH / 4; ++i) {
        float4 w = wp[i];
        s += w.x * hrow[i * 4] + w.y * hrow[i * 4 + 1] + w.z * hrow[i * 4 + 2] + w.w * hrow[i * 4 + 3];
    }
    out[b * 128 + o] = s + fc_b[o];
}

extern "C" void kernel_launch(void* const* d_in, const int* in_sizes, int n_in,
                              void* d_out, int out_size) {
    const float* x    = (const float*)d_in[0];
    const float* Wx   = (const float*)d_in[1];
    const float* bW   = (const float*)d_in[2];
    const float* Wh   = (const float*)d_in[3];
    const float* bU   = (const float*)d_in[4];
    const float* fc_w = (const float*)d_in[5];
    const float* fc_b = (const float*)d_in[6];
    float* out = (float*)d_out;

    cudaFuncSetAttribute(lstm_xproj, cudaFuncAttributeMaxDynamicSharedMemorySize, P1_SMEM);
    cudaFuncSetAttribute(lstm_rec,   cudaFuncAttributeMaxDynamicSharedMemorySize, P2_SMEM);

    lstm_prep_w<<<2048, 256>>>(Wx, Wh, bW, bU);
    lstm_prep_x<<<4096, 256>>>(x);
    lstm_xproj<<<dim3(32, 1024), 256, P1_SMEM>>>();
    lstm_rec<<<NCTA2, 512, P2_SMEM>>>();
    lstm_head<<<128, 128>>>(fc_w, fc_b, out);
}